// round 2
// baseline (speedup 1.0000x reference)
#include <cuda_runtime.h>

#define NN 16384
#define NE 262144
#define HH 4
#define FF 128
#define D1 512          // HEADS*HID
#define SLOPE 0.2f

// ---------------- scratch (static device allocations) ----------------
__device__ float g_fs1[(size_t)NN * D1];
__device__ float g_fd1[(size_t)NN * D1];
__device__ float g_h1 [(size_t)NN * D1];
__device__ float g_fs2[(size_t)NN * FF];
__device__ float g_fd2[(size_t)NN * FF];
__device__ float g_h2 [(size_t)NN * FF];
__device__ float g_sc1[(size_t)NE * HH];
__device__ float g_sc2[NE];
__device__ int   g_cnt[NN];
__device__ int   g_cur[NN];
__device__ int   g_rs [NN + 1];
__device__ int   g_eid[NE];

__device__ __forceinline__ float lrelu(float x) { return x > 0.f ? x : SLOPE * x; }
__device__ __forceinline__ float elu_f(float x) { return x > 0.f ? x : expm1f(x); }

// ---------------- GEMM: C[M,N] = A[M,K] @ B[K,N] + bias ----------------
// 64x64 tile, BK=16, 256 threads, 4x4 per thread. M%64==0, N%64==0, K%16==0.
__global__ void gemm_bias(const float* __restrict__ A, const float* __restrict__ B,
                          const float* __restrict__ bias, float* __restrict__ C,
                          int M, int N, int K)
{
    __shared__ float As[16][64];
    __shared__ float Bs[16][68];
    const int tid  = threadIdx.x;
    const int m0   = blockIdx.y * 64;
    const int n0   = blockIdx.x * 64;
    const int trow = (tid >> 4) << 2;
    const int tcol = (tid & 15) << 2;
    const int la_m = tid >> 2;          // 0..63
    const int la_k = (tid & 3) << 2;    // 0,4,8,12
    const int lb_k = tid >> 4;          // 0..15
    const int lb_n = (tid & 15) << 2;   // 0..60

    float acc[4][4] = {};

    for (int k0 = 0; k0 < K; k0 += 16) {
        float4 a4 = *(const float4*)&A[(size_t)(m0 + la_m) * K + k0 + la_k];
        As[la_k + 0][la_m] = a4.x;
        As[la_k + 1][la_m] = a4.y;
        As[la_k + 2][la_m] = a4.z;
        As[la_k + 3][la_m] = a4.w;
        *(float4*)&Bs[lb_k][lb_n] = *(const float4*)&B[(size_t)(k0 + lb_k) * N + n0 + lb_n];
        __syncthreads();
        #pragma unroll
        for (int k = 0; k < 16; k++) {
            float4 av = *(const float4*)&As[k][trow];
            float4 bv = *(const float4*)&Bs[k][tcol];
            float ar[4] = {av.x, av.y, av.z, av.w};
            float br[4] = {bv.x, bv.y, bv.z, bv.w};
            #pragma unroll
            for (int i = 0; i < 4; i++)
                #pragma unroll
                for (int j = 0; j < 4; j++)
                    acc[i][j] = fmaf(ar[i], br[j], acc[i][j]);
        }
        __syncthreads();
    }
    float4 bv = *(const float4*)&bias[n0 + tcol];
    #pragma unroll
    for (int i = 0; i < 4; i++) {
        float4 o = make_float4(acc[i][0] + bv.x, acc[i][1] + bv.y,
                               acc[i][2] + bv.z, acc[i][3] + bv.w);
        *(float4*)&C[(size_t)(m0 + trow + i) * N + n0 + tcol] = o;
    }
}

// ---------------- CSR build (group edges by dst) ----------------
__global__ void csr_zero()
{
    int i = blockIdx.x * blockDim.x + threadIdx.x;
    if (i < NN) { g_cnt[i] = 0; g_cur[i] = 0; }
}
__global__ void csr_hist(const int* __restrict__ dst)
{
    int e = blockIdx.x * blockDim.x + threadIdx.x;
    if (e < NE) atomicAdd(&g_cnt[dst[e]], 1);
}
__global__ void csr_scan()   // single block, 1024 threads, 16 vals each
{
    __shared__ int sh[1024];
    int t = threadIdx.x;
    int base = t * 16;
    int v[16];
    int s = 0;
    #pragma unroll
    for (int j = 0; j < 16; j++) { s += g_cnt[base + j]; v[j] = s; }
    sh[t] = s;
    __syncthreads();
    for (int off = 1; off < 1024; off <<= 1) {
        int x = (t >= off) ? sh[t - off] : 0;
        __syncthreads();
        sh[t] += x;
        __syncthreads();
    }
    int excl = (t > 0) ? sh[t - 1] : 0;
    if (t == 0) g_rs[0] = 0;
    #pragma unroll
    for (int j = 0; j < 16; j++) g_rs[base + j + 1] = excl + v[j];
}
__global__ void csr_scatter(const int* __restrict__ dst)
{
    int e = blockIdx.x * blockDim.x + threadIdx.x;
    if (e < NE) {
        int d = dst[e];
        int p = atomicAdd(&g_cur[d], 1);
        g_eid[g_rs[d] + p] = e;
    }
}

// ---------------- layer-1 edge scores: warp per edge ----------------
__global__ void score1(const int* __restrict__ src, const int* __restrict__ dst,
                       const float* __restrict__ attn)
{
    int gw   = (blockIdx.x * blockDim.x + threadIdx.x) >> 5;
    int lane = threadIdx.x & 31;
    if (gw >= NE) return;
    int s = src[gw], d = dst[gw];
    const float4* fs = (const float4*)(g_fs1 + (size_t)s * D1);
    const float4* fd = (const float4*)(g_fd1 + (size_t)d * D1);
    const float4* at = (const float4*)attn;
    #pragma unroll
    for (int h = 0; h < HH; h++) {
        float4 a = fs[h * 32 + lane];
        float4 b = fd[h * 32 + lane];
        float4 w = at[h * 32 + lane];
        float v = lrelu(a.x + b.x) * w.x + lrelu(a.y + b.y) * w.y
                + lrelu(a.z + b.z) * w.z + lrelu(a.w + b.w) * w.w;
        #pragma unroll
        for (int o = 16; o; o >>= 1) v += __shfl_xor_sync(0xffffffffu, v, o);
        if (lane == 0) g_sc1[(size_t)gw * HH + h] = v;
    }
}

// ---------------- layer-1 softmax + aggregation + ELU: block(128) per node ----
__global__ void agg1(const int* __restrict__ src)
{
    int n    = blockIdx.x;
    int tid  = threadIdx.x;
    int lane = tid & 31;
    int w    = tid >> 5;         // head id
    __shared__ float sm[HH], sinv[HH];
    int rs  = g_rs[n];
    int deg = g_rs[n + 1] - rs;

    float mx = -1e30f;
    for (int i = lane; i < deg; i += 32)
        mx = fmaxf(mx, g_sc1[(size_t)g_eid[rs + i] * HH + w]);
    #pragma unroll
    for (int o = 16; o; o >>= 1) mx = fmaxf(mx, __shfl_xor_sync(0xffffffffu, mx, o));
    float sum = 0.f;
    for (int i = lane; i < deg; i += 32)
        sum += __expf(g_sc1[(size_t)g_eid[rs + i] * HH + w] - mx);
    #pragma unroll
    for (int o = 16; o; o >>= 1) sum += __shfl_xor_sync(0xffffffffu, sum, o);
    if (lane == 0) { sm[w] = mx; sinv[w] = sum > 0.f ? 1.f / sum : 0.f; }
    __syncthreads();
    float m = sm[w], inv = sinv[w];

    float4 acc = make_float4(0.f, 0.f, 0.f, 0.f);
    for (int i = 0; i < deg; i++) {
        int e = g_eid[rs + i];
        float a = __expf(g_sc1[(size_t)e * HH + w] - m) * inv;
        float4 f = *(const float4*)(g_fs1 + (size_t)src[e] * D1 + tid * 4);
        acc.x = fmaf(a, f.x, acc.x);
        acc.y = fmaf(a, f.y, acc.y);
        acc.z = fmaf(a, f.z, acc.z);
        acc.w = fmaf(a, f.w, acc.w);
    }
    float4 o = make_float4(elu_f(acc.x), elu_f(acc.y), elu_f(acc.z), elu_f(acc.w));
    *(float4*)(g_h1 + (size_t)n * D1 + tid * 4) = o;
}

// ---------------- layer-2 edge scores: warp per edge ----------------
__global__ void score2(const int* __restrict__ src, const int* __restrict__ dst,
                       const float* __restrict__ attn)
{
    int gw   = (blockIdx.x * blockDim.x + threadIdx.x) >> 5;
    int lane = threadIdx.x & 31;
    if (gw >= NE) return;
    int s = src[gw], d = dst[gw];
    float4 a = *(const float4*)(g_fs2 + (size_t)s * FF + lane * 4);
    float4 b = *(const float4*)(g_fd2 + (size_t)d * FF + lane * 4);
    float4 w = *(const float4*)(attn + lane * 4);
    float v = lrelu(a.x + b.x) * w.x + lrelu(a.y + b.y) * w.y
            + lrelu(a.z + b.z) * w.z + lrelu(a.w + b.w) * w.w;
    #pragma unroll
    for (int o = 16; o; o >>= 1) v += __shfl_xor_sync(0xffffffffu, v, o);
    if (lane == 0) g_sc2[gw] = v;
}

// ---------------- layer-2 softmax + aggregation + ELU: warp per node ----------
__global__ void agg2(const int* __restrict__ src)
{
    int n    = blockIdx.x * 8 + (threadIdx.x >> 5);
    int lane = threadIdx.x & 31;
    int rs   = g_rs[n];
    int deg  = g_rs[n + 1] - rs;

    float mx = -1e30f;
    for (int i = lane; i < deg; i += 32)
        mx = fmaxf(mx, g_sc2[g_eid[rs + i]]);
    #pragma unroll
    for (int o = 16; o; o >>= 1) mx = fmaxf(mx, __shfl_xor_sync(0xffffffffu, mx, o));
    float sum = 0.f;
    for (int i = lane; i < deg; i += 32)
        sum += __expf(g_sc2[g_eid[rs + i]] - mx);
    #pragma unroll
    for (int o = 16; o; o >>= 1) sum += __shfl_xor_sync(0xffffffffu, sum, o);
    float inv = sum > 0.f ? 1.f / sum : 0.f;

    float4 acc = make_float4(0.f, 0.f, 0.f, 0.f);
    for (int i = 0; i < deg; i++) {
        int e = g_eid[rs + i];
        float a = __expf(g_sc2[e] - mx) * inv;
        float4 f = *(const float4*)(g_fs2 + (size_t)src[e] * FF + lane * 4);
        acc.x = fmaf(a, f.x, acc.x);
        acc.y = fmaf(a, f.y, acc.y);
        acc.z = fmaf(a, f.z, acc.z);
        acc.w = fmaf(a, f.w, acc.w);
    }
    float4 o = make_float4(elu_f(acc.x), elu_f(acc.y), elu_f(acc.z), elu_f(acc.w));
    *(float4*)(g_h2 + (size_t)n * FF + lane * 4) = o;
}

// ---------------- launch ----------------
extern "C" void kernel_launch(void* const* d_in, const int* in_sizes, int n_in,
                              void* d_out, int out_size)
{
    const float* feat  = (const float*)d_in[0];
    const int*   src   = (const int*)  d_in[1];
    const int*   dst   = (const int*)  d_in[2];
    const float* W1s   = (const float*)d_in[3];
    const float* b1s   = (const float*)d_in[4];
    const float* W1d   = (const float*)d_in[5];
    const float* b1d   = (const float*)d_in[6];
    const float* attn1 = (const float*)d_in[7];
    const float* W2s   = (const float*)d_in[8];
    const float* b2s   = (const float*)d_in[9];
    const float* W2d   = (const float*)d_in[10];
    const float* b2d   = (const float*)d_in[11];
    const float* attn2 = (const float*)d_in[12];
    const float* Wn    = (const float*)d_in[13];
    const float* bn    = (const float*)d_in[14];
    float* out = (float*)d_out;

    float *fs1, *fd1, *h1, *fs2, *fd2, *h2;
    cudaGetSymbolAddress((void**)&fs1, g_fs1);
    cudaGetSymbolAddress((void**)&fd1, g_fd1);
    cudaGetSymbolAddress((void**)&h1,  g_h1);
    cudaGetSymbolAddress((void**)&fs2, g_fs2);
    cudaGetSymbolAddress((void**)&fd2, g_fd2);
    cudaGetSymbolAddress((void**)&h2,  g_h2);

    // layer-1 projections
    gemm_bias<<<dim3(D1 / 64, NN / 64), 256>>>(feat, W1s, b1s, fs1, NN, D1, FF);
    gemm_bias<<<dim3(D1 / 64, NN / 64), 256>>>(feat, W1d, b1d, fd1, NN, D1, FF);

    // CSR by dst
    csr_zero   <<<NN / 256, 256>>>();
    csr_hist   <<<NE / 256, 256>>>(dst);
    csr_scan   <<<1, 1024>>>();
    csr_scatter<<<NE / 256, 256>>>(dst);

    // layer-1 edge softmax + aggregation (+ ELU)
    score1<<<NE / 8, 256>>>(src, dst, attn1);
    agg1  <<<NN, 128>>>(src);

    // layer-2 projections
    gemm_bias<<<dim3(FF / 64, NN / 64), 256>>>(h1, W2s, b2s, fs2, NN, FF, D1);
    gemm_bias<<<dim3(FF / 64, NN / 64), 256>>>(h1, W2d, b2d, fd2, NN, FF, D1);

    // layer-2 edge softmax + aggregation (+ ELU)
    score2<<<NE / 8, 256>>>(src, dst, attn2);
    agg2  <<<NN / 8, 256>>>(src);

    // head: [256, 8192] @ [8192, 128] + bn
    gemm_bias<<<dim3(FF / 64, (NN / 64) / 64), 256>>>(h2, Wn, bn, out, NN / 64, FF, 64 * FF);
}

// round 4
// speedup vs baseline: 2.0142x; 2.0142x over previous
#include <cuda_runtime.h>

#define NN 16384
#define NE 262144
#define HH 4
#define FF 128
#define D1 512          // HEADS*HID
#define SLOPE 0.2f
#define SK 32           // split-K factor for head GEMM

// ---------------- scratch (static device allocations) ----------------
__device__ float g_fs1[(size_t)NN * D1];
__device__ float g_fd1[(size_t)NN * D1];
__device__ float g_h1 [(size_t)NN * D1];
__device__ float g_fs2[(size_t)NN * FF];
__device__ float g_fd2[(size_t)NN * FF];
__device__ float g_h2 [(size_t)NN * FF];
__device__ float g_sc1[(size_t)NE * HH];
__device__ float g_sc2[NE];
__device__ float g_part[(size_t)SK * 256 * 128];
__device__ int   g_cnt[NN];
__device__ int   g_cur[NN];
__device__ int   g_rs [NN + 1];
__device__ int   g_eid[NE];

__device__ __forceinline__ float lrelu(float x) { return x > 0.f ? x : SLOPE * x; }
__device__ __forceinline__ float elu_f(float x) { return x > 0.f ? x : expm1f(x); }

// ============ GEMM: C[M,N] = A[M,K] @ B[K,N] + bias ============
// 128x128 tile, BK=16, 256 threads, 8x8 per thread, double-buffered smem.
// Requires M%128==0, N%128==0, K%16==0.
__global__ __launch_bounds__(256) void gemm128(
    const float* __restrict__ A, const float* __restrict__ B,
    const float* __restrict__ bias, float* __restrict__ C,
    int M, int N, int K)
{
    __shared__ float As[2][16][128];
    __shared__ float Bs[2][16][128];
    const int tid  = threadIdx.x;
    const int m0   = blockIdx.y * 128;
    const int n0   = blockIdx.x * 128;
    const int la_m = tid >> 1;            // 0..127
    const int la_k = (tid & 1) << 3;      // 0 or 8
    const int lb_k = tid >> 4;            // 0..15
    const int lb_n = (tid & 15) << 3;     // 0..120
    const int ty   = tid >> 4;            // 0..15  -> rows ty*8..
    const int tx   = tid & 15;            // 0..15  -> cols tx*8..

    const float* Ap = A + (size_t)(m0 + la_m) * K + la_k;
    const float* Bp = B + (size_t)lb_k * N + n0 + lb_n;

    float4 ra0 = *(const float4*)(Ap);
    float4 ra1 = *(const float4*)(Ap + 4);
    float4 rb0 = *(const float4*)(Bp);
    float4 rb1 = *(const float4*)(Bp + 4);

    float acc[8][8] = {};

    // stage first tile
    As[0][la_k + 0][la_m] = ra0.x; As[0][la_k + 1][la_m] = ra0.y;
    As[0][la_k + 2][la_m] = ra0.z; As[0][la_k + 3][la_m] = ra0.w;
    As[0][la_k + 4][la_m] = ra1.x; As[0][la_k + 5][la_m] = ra1.y;
    As[0][la_k + 6][la_m] = ra1.z; As[0][la_k + 7][la_m] = ra1.w;
    *(float4*)&Bs[0][lb_k][lb_n]     = rb0;
    *(float4*)&Bs[0][lb_k][lb_n + 4] = rb1;
    __syncthreads();

    const int nsteps = K >> 4;
    for (int s = 0; s < nsteps; s++) {
        const int buf = s & 1;
        if (s + 1 < nsteps) {
            const float* Ap2 = Ap + (s + 1) * 16;
            const float* Bp2 = Bp + (size_t)(s + 1) * 16 * N;
            ra0 = *(const float4*)(Ap2);
            ra1 = *(const float4*)(Ap2 + 4);
            rb0 = *(const float4*)(Bp2);
            rb1 = *(const float4*)(Bp2 + 4);
        }
        #pragma unroll
        for (int k = 0; k < 16; k++) {
            float a[8], b[8];
            *(float4*)&a[0] = *(const float4*)&As[buf][k][ty * 8];
            *(float4*)&a[4] = *(const float4*)&As[buf][k][ty * 8 + 4];
            *(float4*)&b[0] = *(const float4*)&Bs[buf][k][tx * 8];
            *(float4*)&b[4] = *(const float4*)&Bs[buf][k][tx * 8 + 4];
            #pragma unroll
            for (int i = 0; i < 8; i++)
                #pragma unroll
                for (int j = 0; j < 8; j++)
                    acc[i][j] = fmaf(a[i], b[j], acc[i][j]);
        }
        if (s + 1 < nsteps) {
            const int nb = buf ^ 1;
            As[nb][la_k + 0][la_m] = ra0.x; As[nb][la_k + 1][la_m] = ra0.y;
            As[nb][la_k + 2][la_m] = ra0.z; As[nb][la_k + 3][la_m] = ra0.w;
            As[nb][la_k + 4][la_m] = ra1.x; As[nb][la_k + 5][la_m] = ra1.y;
            As[nb][la_k + 6][la_m] = ra1.z; As[nb][la_k + 7][la_m] = ra1.w;
            *(float4*)&Bs[nb][lb_k][lb_n]     = rb0;
            *(float4*)&Bs[nb][lb_k][lb_n + 4] = rb1;
        }
        __syncthreads();
    }

    float4 bv0 = *(const float4*)&bias[n0 + tx * 8];
    float4 bv1 = *(const float4*)&bias[n0 + tx * 8 + 4];
    #pragma unroll
    for (int i = 0; i < 8; i++) {
        float* cp = C + (size_t)(m0 + ty * 8 + i) * N + n0 + tx * 8;
        float4 o0 = make_float4(acc[i][0] + bv0.x, acc[i][1] + bv0.y,
                                acc[i][2] + bv0.z, acc[i][3] + bv0.w);
        float4 o1 = make_float4(acc[i][4] + bv1.x, acc[i][5] + bv1.y,
                                acc[i][6] + bv1.z, acc[i][7] + bv1.w);
        *(float4*)cp       = o0;
        *(float4*)(cp + 4) = o1;
    }
}

// ============ Split-K GEMM partial: P[z] = A[:,zc:(z+1)c] @ B[zc:(z+1)c,:] ====
// Same tiling as gemm128; blockIdx.z = K-chunk. No bias; writes partials.
__global__ __launch_bounds__(256) void gemm_sk(
    const float* __restrict__ A, const float* __restrict__ B,
    float* __restrict__ P, int M, int N, int K, int kchunk)
{
    __shared__ float As[2][16][128];
    __shared__ float Bs[2][16][128];
    const int tid  = threadIdx.x;
    const int m0   = blockIdx.y * 128;
    const int n0   = blockIdx.x * 128;
    const int kz   = blockIdx.z * kchunk;
    const int la_m = tid >> 1;
    const int la_k = (tid & 1) << 3;
    const int lb_k = tid >> 4;
    const int lb_n = (tid & 15) << 3;
    const int ty   = tid >> 4;
    const int tx   = tid & 15;

    const float* Ap = A + (size_t)(m0 + la_m) * K + kz + la_k;
    const float* Bp = B + (size_t)(kz + lb_k) * N + n0 + lb_n;

    float4 ra0 = *(const float4*)(Ap);
    float4 ra1 = *(const float4*)(Ap + 4);
    float4 rb0 = *(const float4*)(Bp);
    float4 rb1 = *(const float4*)(Bp + 4);

    float acc[8][8] = {};

    As[0][la_k + 0][la_m] = ra0.x; As[0][la_k + 1][la_m] = ra0.y;
    As[0][la_k + 2][la_m] = ra0.z; As[0][la_k + 3][la_m] = ra0.w;
    As[0][la_k + 4][la_m] = ra1.x; As[0][la_k + 5][la_m] = ra1.y;
    As[0][la_k + 6][la_m] = ra1.z; As[0][la_k + 7][la_m] = ra1.w;
    *(float4*)&Bs[0][lb_k][lb_n]     = rb0;
    *(float4*)&Bs[0][lb_k][lb_n + 4] = rb1;
    __syncthreads();

    const int nsteps = kchunk >> 4;
    for (int s = 0; s < nsteps; s++) {
        const int buf = s & 1;
        if (s + 1 < nsteps) {
            const float* Ap2 = Ap + (s + 1) * 16;
            const float* Bp2 = Bp + (size_t)(s + 1) * 16 * N;
            ra0 = *(const float4*)(Ap2);
            ra1 = *(const float4*)(Ap2 + 4);
            rb0 = *(const float4*)(Bp2);
            rb1 = *(const float4*)(Bp2 + 4);
        }
        #pragma unroll
        for (int k = 0; k < 16; k++) {
            float a[8], b[8];
            *(float4*)&a[0] = *(const float4*)&As[buf][k][ty * 8];
            *(float4*)&a[4] = *(const float4*)&As[buf][k][ty * 8 + 4];
            *(float4*)&b[0] = *(const float4*)&Bs[buf][k][tx * 8];
            *(float4*)&b[4] = *(const float4*)&Bs[buf][k][tx * 8 + 4];
            #pragma unroll
            for (int i = 0; i < 8; i++)
                #pragma unroll
                for (int j = 0; j < 8; j++)
                    acc[i][j] = fmaf(a[i], b[j], acc[i][j]);
        }
        if (s + 1 < nsteps) {
            const int nb = buf ^ 1;
            As[nb][la_k + 0][la_m] = ra0.x; As[nb][la_k + 1][la_m] = ra0.y;
            As[nb][la_k + 2][la_m] = ra0.z; As[nb][la_k + 3][la_m] = ra0.w;
            As[nb][la_k + 4][la_m] = ra1.x; As[nb][la_k + 5][la_m] = ra1.y;
            As[nb][la_k + 6][la_m] = ra1.z; As[nb][la_k + 7][la_m] = ra1.w;
            *(float4*)&Bs[nb][lb_k][lb_n]     = rb0;
            *(float4*)&Bs[nb][lb_k][lb_n + 4] = rb1;
        }
        __syncthreads();
    }

    float* Pz = P + (size_t)blockIdx.z * M * N;
    #pragma unroll
    for (int i = 0; i < 8; i++) {
        float* cp = Pz + (size_t)(m0 + ty * 8 + i) * N + n0 + tx * 8;
        *(float4*)cp       = make_float4(acc[i][0], acc[i][1], acc[i][2], acc[i][3]);
        *(float4*)(cp + 4) = make_float4(acc[i][4], acc[i][5], acc[i][6], acc[i][7]);
    }
}

__global__ void sk_reduce(const float* __restrict__ P, const float* __restrict__ bias,
                          float* __restrict__ C, int MN, int N, int nz)
{
    int i = blockIdx.x * blockDim.x + threadIdx.x;
    if (i >= MN) return;
    float s = 0.f;
    for (int z = 0; z < nz; z++) s += P[(size_t)z * MN + i];
    C[i] = s + bias[i % N];
}

// ---------------- CSR build (group edges by dst) ----------------
__global__ void csr_zero()
{
    int i = blockIdx.x * blockDim.x + threadIdx.x;
    if (i < NN) { g_cnt[i] = 0; g_cur[i] = 0; }
}
__global__ void csr_hist(const int* __restrict__ dst)
{
    int e = blockIdx.x * blockDim.x + threadIdx.x;
    if (e < NE) atomicAdd(&g_cnt[dst[e]], 1);
}
__global__ void csr_scan()   // single block, 1024 threads, 16 vals each
{
    __shared__ int sh[1024];
    int t = threadIdx.x;
    int base = t * 16;
    int v[16];
    int s = 0;
    #pragma unroll
    for (int j = 0; j < 16; j++) { s += g_cnt[base + j]; v[j] = s; }
    sh[t] = s;
    __syncthreads();
    for (int off = 1; off < 1024; off <<= 1) {
        int x = (t >= off) ? sh[t - off] : 0;
        __syncthreads();
        sh[t] += x;
        __syncthreads();
    }
    int excl = (t > 0) ? sh[t - 1] : 0;
    if (t == 0) g_rs[0] = 0;
    #pragma unroll
    for (int j = 0; j < 16; j++) g_rs[base + j + 1] = excl + v[j];
}
__global__ void csr_scatter(const int* __restrict__ dst)
{
    int e = blockIdx.x * blockDim.x + threadIdx.x;
    if (e < NE) {
        int d = dst[e];
        int p = atomicAdd(&g_cur[d], 1);
        g_eid[g_rs[d] + p] = e;
    }
}

// ---------------- layer-1 edge scores: warp per edge ----------------
__global__ void score1(const int* __restrict__ src, const int* __restrict__ dst,
                       const float* __restrict__ attn)
{
    int gw   = (blockIdx.x * blockDim.x + threadIdx.x) >> 5;
    int lane = threadIdx.x & 31;
    if (gw >= NE) return;
    int s = src[gw], d = dst[gw];
    const float4* fs = (const float4*)(g_fs1 + (size_t)s * D1);
    const float4* fd = (const float4*)(g_fd1 + (size_t)d * D1);
    const float4* at = (const float4*)attn;
    #pragma unroll
    for (int h = 0; h < HH; h++) {
        float4 a = fs[h * 32 + lane];
        float4 b = fd[h * 32 + lane];
        float4 w = at[h * 32 + lane];
        float v = lrelu(a.x + b.x) * w.x + lrelu(a.y + b.y) * w.y
                + lrelu(a.z + b.z) * w.z + lrelu(a.w + b.w) * w.w;
        #pragma unroll
        for (int o = 16; o; o >>= 1) v += __shfl_xor_sync(0xffffffffu, v, o);
        if (lane == 0) g_sc1[(size_t)gw * HH + h] = v;
    }
}

// ---------------- layer-1 softmax + aggregation + ELU: block(128) per node ----
__global__ void agg1(const int* __restrict__ src)
{
    int n    = blockIdx.x;
    int tid  = threadIdx.x;
    int lane = tid & 31;
    int w    = tid >> 5;         // head id
    __shared__ float sm[HH], sinv[HH];
    int rs  = g_rs[n];
    int deg = g_rs[n + 1] - rs;

    float mx = -1e30f;
    for (int i = lane; i < deg; i += 32)
        mx = fmaxf(mx, g_sc1[(size_t)g_eid[rs + i] * HH + w]);
    #pragma unroll
    for (int o = 16; o; o >>= 1) mx = fmaxf(mx, __shfl_xor_sync(0xffffffffu, mx, o));
    float sum = 0.f;
    for (int i = lane; i < deg; i += 32)
        sum += __expf(g_sc1[(size_t)g_eid[rs + i] * HH + w] - mx);
    #pragma unroll
    for (int o = 16; o; o >>= 1) sum += __shfl_xor_sync(0xffffffffu, sum, o);
    if (lane == 0) { sm[w] = mx; sinv[w] = sum > 0.f ? 1.f / sum : 0.f; }
    __syncthreads();
    float m = sm[w], inv = sinv[w];

    float4 acc = make_float4(0.f, 0.f, 0.f, 0.f);
    for (int i = 0; i < deg; i++) {
        int e = g_eid[rs + i];
        float a = __expf(g_sc1[(size_t)e * HH + w] - m) * inv;
        float4 f = *(const float4*)(g_fs1 + (size_t)src[e] * D1 + tid * 4);
        acc.x = fmaf(a, f.x, acc.x);
        acc.y = fmaf(a, f.y, acc.y);
        acc.z = fmaf(a, f.z, acc.z);
        acc.w = fmaf(a, f.w, acc.w);
    }
    float4 o = make_float4(elu_f(acc.x), elu_f(acc.y), elu_f(acc.z), elu_f(acc.w));
    *(float4*)(g_h1 + (size_t)n * D1 + tid * 4) = o;
}

// ---------------- layer-2 edge scores: warp per edge ----------------
__global__ void score2(const int* __restrict__ src, const int* __restrict__ dst,
                       const float* __restrict__ attn)
{
    int gw   = (blockIdx.x * blockDim.x + threadIdx.x) >> 5;
    int lane = threadIdx.x & 31;
    if (gw >= NE) return;
    int s = src[gw], d = dst[gw];
    float4 a = *(const float4*)(g_fs2 + (size_t)s * FF + lane * 4);
    float4 b = *(const float4*)(g_fd2 + (size_t)d * FF + lane * 4);
    float4 w = *(const float4*)(attn + lane * 4);
    float v = lrelu(a.x + b.x) * w.x + lrelu(a.y + b.y) * w.y
            + lrelu(a.z + b.z) * w.z + lrelu(a.w + b.w) * w.w;
    #pragma unroll
    for (int o = 16; o; o >>= 1) v += __shfl_xor_sync(0xffffffffu, v, o);
    if (lane == 0) g_sc2[gw] = v;
}

// ---------------- layer-2 softmax + aggregation + ELU: warp per node ----------
__global__ void agg2(const int* __restrict__ src)
{
    int n    = blockIdx.x * 8 + (threadIdx.x >> 5);
    int lane = threadIdx.x & 31;
    int rs   = g_rs[n];
    int deg  = g_rs[n + 1] - rs;

    float mx = -1e30f;
    for (int i = lane; i < deg; i += 32)
        mx = fmaxf(mx, g_sc2[g_eid[rs + i]]);
    #pragma unroll
    for (int o = 16; o; o >>= 1) mx = fmaxf(mx, __shfl_xor_sync(0xffffffffu, mx, o));
    float sum = 0.f;
    for (int i = lane; i < deg; i += 32)
        sum += __expf(g_sc2[g_eid[rs + i]] - mx);
    #pragma unroll
    for (int o = 16; o; o >>= 1) sum += __shfl_xor_sync(0xffffffffu, sum, o);
    float inv = sum > 0.f ? 1.f / sum : 0.f;

    float4 acc = make_float4(0.f, 0.f, 0.f, 0.f);
    for (int i = 0; i < deg; i++) {
        int e = g_eid[rs + i];
        float a = __expf(g_sc2[e] - mx) * inv;
        float4 f = *(const float4*)(g_fs2 + (size_t)src[e] * FF + lane * 4);
        acc.x = fmaf(a, f.x, acc.x);
        acc.y = fmaf(a, f.y, acc.y);
        acc.z = fmaf(a, f.z, acc.z);
        acc.w = fmaf(a, f.w, acc.w);
    }
    float4 o = make_float4(elu_f(acc.x), elu_f(acc.y), elu_f(acc.z), elu_f(acc.w));
    *(float4*)(g_h2 + (size_t)n * FF + lane * 4) = o;
}

// ---------------- launch ----------------
extern "C" void kernel_launch(void* const* d_in, const int* in_sizes, int n_in,
                              void* d_out, int out_size)
{
    const float* feat  = (const float*)d_in[0];
    const int*   src   = (const int*)  d_in[1];
    const int*   dst   = (const int*)  d_in[2];
    const float* W1s   = (const float*)d_in[3];
    const float* b1s   = (const float*)d_in[4];
    const float* W1d   = (const float*)d_in[5];
    const float* b1d   = (const float*)d_in[6];
    const float* attn1 = (const float*)d_in[7];
    const float* W2s   = (const float*)d_in[8];
    const float* b2s   = (const float*)d_in[9];
    const float* W2d   = (const float*)d_in[10];
    const float* b2d   = (const float*)d_in[11];
    const float* attn2 = (const float*)d_in[12];
    const float* Wn    = (const float*)d_in[13];
    const float* bn    = (const float*)d_in[14];
    float* out = (float*)d_out;

    float *fs1, *fd1, *h1, *fs2, *fd2, *h2, *part;
    cudaGetSymbolAddress((void**)&fs1,  g_fs1);
    cudaGetSymbolAddress((void**)&fd1,  g_fd1);
    cudaGetSymbolAddress((void**)&h1,   g_h1);
    cudaGetSymbolAddress((void**)&fs2,  g_fs2);
    cudaGetSymbolAddress((void**)&fd2,  g_fd2);
    cudaGetSymbolAddress((void**)&h2,   g_h2);
    cudaGetSymbolAddress((void**)&part, g_part);

    // layer-1 projections: [16384,128] @ [128,512]
    gemm128<<<dim3(D1 / 128, NN / 128), 256>>>(feat, W1s, b1s, fs1, NN, D1, FF);
    gemm128<<<dim3(D1 / 128, NN / 128), 256>>>(feat, W1d, b1d, fd1, NN, D1, FF);

    // CSR by dst
    csr_zero   <<<NN / 256, 256>>>();
    csr_hist   <<<NE / 256, 256>>>(dst);
    csr_scan   <<<1, 1024>>>();
    csr_scatter<<<NE / 256, 256>>>(dst);

    // layer-1 edge softmax + aggregation (+ ELU)
    score1<<<NE / 8, 256>>>(src, dst, attn1);
    agg1  <<<NN, 128>>>(src);

    // layer-2 projections: [16384,512] @ [512,128]
    gemm128<<<dim3(FF / 128, NN / 128), 256>>>(h1, W2s, b2s, fs2, NN, FF, D1);
    gemm128<<<dim3(FF / 128, NN / 128), 256>>>(h1, W2d, b2d, fd2, NN, FF, D1);

    // layer-2 edge softmax + aggregation (+ ELU)
    score2<<<NE / 8, 256>>>(src, dst, attn2);
    agg2  <<<NN / 8, 256>>>(src);

    // head: [256, 8192] @ [8192, 128] + bn — 32-way split-K then reduce
    gemm_sk<<<dim3(1, 2, SK), 256>>>(h2, Wn, part, 256, FF, 64 * FF, (64 * FF) / SK);
    sk_reduce<<<(256 * FF) / 256, 256>>>(part, bn, out, 256 * FF, FF, SK);
}

// round 12
// speedup vs baseline: 2.4541x; 1.2184x over previous
#include <cuda_runtime.h>
#include <cuda_bf16.h>
#include <cstdint>

#define NN 16384
#define NE 262144
#define HH 4
#define FF 128
#define D1 512          // HEADS*HID
#define SLOPE 0.2f
#define SK 32           // split-K factor for head GEMM

// ---------------- scratch (static device allocations) ----------------
__device__ float g_fs1[(size_t)NN * D1];
__device__ float g_fd1[(size_t)NN * D1];
__device__ float g_h1 [(size_t)NN * D1];
__device__ float g_fs2[(size_t)NN * FF];
__device__ float g_fd2[(size_t)NN * FF];
__device__ float g_h2 [(size_t)NN * FF];
__device__ float g_sc1[(size_t)NE * HH];
__device__ float g_sc2[NE];
__device__ float g_part[(size_t)SK * 256 * 128];
__device__ int   g_cnt[NN];
__device__ int   g_cur[NN];
__device__ int   g_rs [NN + 1];
__device__ int   g_eid[NE];

__device__ __forceinline__ float lrelu(float x) { return x > 0.f ? x : SLOPE * x; }
__device__ __forceinline__ float elu_f(float x) { return x > 0.f ? x : expm1f(x); }

// split fp32 pair -> bf16x2 (hi) and bf16x2 (residual lo); low half = first elem
__device__ __forceinline__ void split_pack(float x0, float x1, uint32_t& hi, uint32_t& lo)
{
    __nv_bfloat16 h0 = __float2bfloat16(x0);
    __nv_bfloat16 h1 = __float2bfloat16(x1);
    __nv_bfloat16 l0 = __float2bfloat16(x0 - __bfloat162float(h0));
    __nv_bfloat16 l1 = __float2bfloat16(x1 - __bfloat162float(h1));
    __nv_bfloat162 H = __halves2bfloat162(h0, h1);
    __nv_bfloat162 L = __halves2bfloat162(l0, l1);
    hi = *reinterpret_cast<uint32_t*>(&H);
    lo = *reinterpret_cast<uint32_t*>(&L);
}

// m16n8k16 row.col bf16 mma, fp32 accumulate (sm_80+ baseline PTX)
__device__ __forceinline__ void mma16816(float* d, const uint32_t* a, const uint32_t* b)
{
    asm volatile(
        "mma.sync.aligned.m16n8k16.row.col.f32.bf16.bf16.f32 "
        "{%0,%1,%2,%3}, {%4,%5,%6,%7}, {%8,%9}, {%0,%1,%2,%3};"
        : "+f"(d[0]), "+f"(d[1]), "+f"(d[2]), "+f"(d[3])
        : "r"(a[0]), "r"(a[1]), "r"(a[2]), "r"(a[3]), "r"(b[0]), "r"(b[1]));
}

// ============ mma.sync GEMM: C[M,N] = A[M,K] @ W[K,N] + bias ============
// 128x128 block tile, 8 warps (4m x 2n), warp tile 32x64, K chunk 32.
// fp32 in/out; internally 3-term bf16 split. M%128==0, N%128==0, K%32==0.
#define LDA 18   // uint32 words per smem row: 16 pairs (32 bf16) + 2 pad

__global__ __launch_bounds__(256) void gemm_mma(
    const float* __restrict__ A, const float* __restrict__ W,
    const float* __restrict__ bias, float* __restrict__ C,
    int M, int N, int K)
{
    __shared__ uint32_t sAhi[128 * LDA], sAlo[128 * LDA];
    __shared__ uint32_t sBhi[128 * LDA], sBlo[128 * LDA];

    const int tid  = threadIdx.x;
    const int wid  = tid >> 5;
    const int lane = tid & 31;
    const int m0   = blockIdx.y * 128;
    const int n0   = blockIdx.x * 128;
    const int wm   = wid >> 1;          // 0..3 -> warp rows wm*32
    const int wn   = wid & 1;           // 0..1 -> warp cols wn*64
    const int lr   = lane >> 2;         // 0..7
    const int lc   = lane & 3;          // 0..3

    float d[2][8][4] = {};              // [mt][nt][frag]

    for (int kc = 0; kc < K; kc += 32) {
        // --- stage A chunk [128 m][32 k] as bf16 hi/lo, k-major ---
        #pragma unroll
        for (int i = 0; i < 8; i++) {
            int q = tid + 256 * i;      // 2048 pairs
            int row = q >> 4, kp = q & 15;
            float2 v = *(const float2*)&A[(size_t)(m0 + row) * K + kc + 2 * kp];
            uint32_t hi, lo;
            split_pack(v.x, v.y, hi, lo);
            sAhi[row * LDA + kp] = hi;
            sAlo[row * LDA + kp] = lo;
        }
        // --- stage B chunk: W[kc..kc+31][n0..n0+127] -> [n][k] k-major ---
        #pragma unroll
        for (int i = 0; i < 8; i++) {
            int q = tid + 256 * i;
            int n = q & 127, kp = q >> 7;
            float w0 = W[(size_t)(kc + 2 * kp)     * N + n0 + n];
            float w1 = W[(size_t)(kc + 2 * kp + 1) * N + n0 + n];
            uint32_t hi, lo;
            split_pack(w0, w1, hi, lo);
            sBhi[n * LDA + kp] = hi;
            sBlo[n * LDA + kp] = lo;
        }
        __syncthreads();

        #pragma unroll
        for (int ks = 0; ks < 2; ks++) {
            const int kb = ks * 8;      // pair offset of this k16 tile
            uint32_t ahi[2][4], alo[2][4];
            #pragma unroll
            for (int mt = 0; mt < 2; mt++) {
                int r = (wm * 32 + mt * 16 + lr) * LDA + kb + lc;
                ahi[mt][0] = sAhi[r];               alo[mt][0] = sAlo[r];
                ahi[mt][1] = sAhi[r + 8 * LDA];     alo[mt][1] = sAlo[r + 8 * LDA];
                ahi[mt][2] = sAhi[r + 4];           alo[mt][2] = sAlo[r + 4];
                ahi[mt][3] = sAhi[r + 8 * LDA + 4]; alo[mt][3] = sAlo[r + 8 * LDA + 4];
            }
            uint32_t bhi[8][2], blo[8][2];
            #pragma unroll
            for (int nt = 0; nt < 8; nt++) {
                int r = (wn * 64 + nt * 8 + lr) * LDA + kb + lc;
                bhi[nt][0] = sBhi[r];     blo[nt][0] = sBlo[r];
                bhi[nt][1] = sBhi[r + 4]; blo[nt][1] = sBlo[r + 4];
            }
            #pragma unroll
            for (int mt = 0; mt < 2; mt++)
                #pragma unroll
                for (int nt = 0; nt < 8; nt++) {
                    mma16816(d[mt][nt], ahi[mt], bhi[nt]);
                    mma16816(d[mt][nt], ahi[mt], blo[nt]);
                    mma16816(d[mt][nt], alo[mt], bhi[nt]);
                }
        }
        __syncthreads();
    }

    // epilogue: c0,c1 at (row, 2*lc+{0,1}), c2,c3 at (row+8, same)
    #pragma unroll
    for (int mt = 0; mt < 2; mt++) {
        int m = m0 + wm * 32 + mt * 16 + lr;
        #pragma unroll
        for (int nt = 0; nt < 8; nt++) {
            int col = n0 + wn * 64 + nt * 8 + 2 * lc;
            float2 bv = *(const float2*)&bias[col];
            float2 o0 = make_float2(d[mt][nt][0] + bv.x, d[mt][nt][1] + bv.y);
            float2 o1 = make_float2(d[mt][nt][2] + bv.x, d[mt][nt][3] + bv.y);
            *(float2*)&C[(size_t)m * N + col]       = o0;
            *(float2*)&C[(size_t)(m + 8) * N + col] = o1;
        }
    }
}

// ============ Split-K GEMM partial (head): P[z] = A[:,zc:(z+1)c] @ B[zc:(z+1)c,:]
__global__ __launch_bounds__(256) void gemm_sk(
    const float* __restrict__ A, const float* __restrict__ B,
    float* __restrict__ P, int M, int N, int K, int kchunk)
{
    __shared__ float As[2][16][128];
    __shared__ float Bs[2][16][128];
    const int tid  = threadIdx.x;
    const int m0   = blockIdx.y * 128;
    const int n0   = blockIdx.x * 128;
    const int kz   = blockIdx.z * kchunk;
    const int la_m = tid >> 1;
    const int la_k = (tid & 1) << 3;
    const int lb_k = tid >> 4;
    const int lb_n = (tid & 15) << 3;
    const int ty   = tid >> 4;
    const int tx   = tid & 15;

    const float* Ap = A + (size_t)(m0 + la_m) * K + kz + la_k;
    const float* Bp = B + (size_t)(kz + lb_k) * N + n0 + lb_n;

    float4 ra0 = *(const float4*)(Ap);
    float4 ra1 = *(const float4*)(Ap + 4);
    float4 rb0 = *(const float4*)(Bp);
    float4 rb1 = *(const float4*)(Bp + 4);

    float acc[8][8] = {};

    As[0][la_k + 0][la_m] = ra0.x; As[0][la_k + 1][la_m] = ra0.y;
    As[0][la_k + 2][la_m] = ra0.z; As[0][la_k + 3][la_m] = ra0.w;
    As[0][la_k + 4][la_m] = ra1.x; As[0][la_k + 5][la_m] = ra1.y;
    As[0][la_k + 6][la_m] = ra1.z; As[0][la_k + 7][la_m] = ra1.w;
    *(float4*)&Bs[0][lb_k][lb_n]     = rb0;
    *(float4*)&Bs[0][lb_k][lb_n + 4] = rb1;
    __syncthreads();

    const int nsteps = kchunk >> 4;
    for (int s = 0; s < nsteps; s++) {
        const int buf = s & 1;
        if (s + 1 < nsteps) {
            const float* Ap2 = Ap + (s + 1) * 16;
            const float* Bp2 = Bp + (size_t)(s + 1) * 16 * N;
            ra0 = *(const float4*)(Ap2);
            ra1 = *(const float4*)(Ap2 + 4);
            rb0 = *(const float4*)(Bp2);
            rb1 = *(const float4*)(Bp2 + 4);
        }
        #pragma unroll
        for (int k = 0; k < 16; k++) {
            float a[8], b[8];
            *(float4*)&a[0] = *(const float4*)&As[buf][k][ty * 8];
            *(float4*)&a[4] = *(const float4*)&As[buf][k][ty * 8 + 4];
            *(float4*)&b[0] = *(const float4*)&Bs[buf][k][tx * 8];
            *(float4*)&b[4] = *(const float4*)&Bs[buf][k][tx * 8 + 4];
            #pragma unroll
            for (int i = 0; i < 8; i++)
                #pragma unroll
                for (int j = 0; j < 8; j++)
                    acc[i][j] = fmaf(a[i], b[j], acc[i][j]);
        }
        if (s + 1 < nsteps) {
            const int nb = buf ^ 1;
            As[nb][la_k + 0][la_m] = ra0.x; As[nb][la_k + 1][la_m] = ra0.y;
            As[nb][la_k + 2][la_m] = ra0.z; As[nb][la_k + 3][la_m] = ra0.w;
            As[nb][la_k + 4][la_m] = ra1.x; As[nb][la_k + 5][la_m] = ra1.y;
            As[nb][la_k + 6][la_m] = ra1.z; As[nb][la_k + 7][la_m] = ra1.w;
            *(float4*)&Bs[nb][lb_k][lb_n]     = rb0;
            *(float4*)&Bs[nb][lb_k][lb_n + 4] = rb1;
        }
        __syncthreads();
    }

    float* Pz = P + (size_t)blockIdx.z * M * N;
    #pragma unroll
    for (int i = 0; i < 8; i++) {
        float* cp = Pz + (size_t)(m0 + ty * 8 + i) * N + n0 + tx * 8;
        *(float4*)cp       = make_float4(acc[i][0], acc[i][1], acc[i][2], acc[i][3]);
        *(float4*)(cp + 4) = make_float4(acc[i][4], acc[i][5], acc[i][6], acc[i][7]);
    }
}

__global__ void sk_reduce(const float* __restrict__ P, const float* __restrict__ bias,
                          float* __restrict__ C, int MN, int N, int nz)
{
    int i = blockIdx.x * blockDim.x + threadIdx.x;
    if (i >= MN) return;
    float s = 0.f;
    for (int z = 0; z < nz; z++) s += P[(size_t)z * MN + i];
    C[i] = s + bias[i % N];
}

// ---------------- CSR build (group edges by dst) ----------------
__global__ void csr_zero()
{
    int i = blockIdx.x * blockDim.x + threadIdx.x;
    if (i < NN) { g_cnt[i] = 0; g_cur[i] = 0; }
}
__global__ void csr_hist(const int* __restrict__ dst)
{
    int e = blockIdx.x * blockDim.x + threadIdx.x;
    if (e < NE) atomicAdd(&g_cnt[dst[e]], 1);
}
__global__ void csr_scan()   // single block, 1024 threads, 16 vals each
{
    __shared__ int sh[1024];
    int t = threadIdx.x;
    int base = t * 16;
    int v[16];
    int s = 0;
    #pragma unroll
    for (int j = 0; j < 16; j++) { s += g_cnt[base + j]; v[j] = s; }
    sh[t] = s;
    __syncthreads();
    for (int off = 1; off < 1024; off <<= 1) {
        int x = (t >= off) ? sh[t - off] : 0;
        __syncthreads();
        sh[t] += x;
        __syncthreads();
    }
    int excl = (t > 0) ? sh[t - 1] : 0;
    if (t == 0) g_rs[0] = 0;
    #pragma unroll
    for (int j = 0; j < 16; j++) g_rs[base + j + 1] = excl + v[j];
}
__global__ void csr_scatter(const int* __restrict__ dst)
{
    int e = blockIdx.x * blockDim.x + threadIdx.x;
    if (e < NE) {
        int d = dst[e];
        int p = atomicAdd(&g_cur[d], 1);
        g_eid[g_rs[d] + p] = e;
    }
}

// ---------------- layer-1 edge scores: warp per edge ----------------
__global__ void score1(const int* __restrict__ src, const int* __restrict__ dst,
                       const float* __restrict__ attn)
{
    int gw   = (blockIdx.x * blockDim.x + threadIdx.x) >> 5;
    int lane = threadIdx.x & 31;
    if (gw >= NE) return;
    int s = src[gw], d = dst[gw];
    const float4* fs = (const float4*)(g_fs1 + (size_t)s * D1);
    const float4* fd = (const float4*)(g_fd1 + (size_t)d * D1);
    const float4* at = (const float4*)attn;
    #pragma unroll
    for (int h = 0; h < HH; h++) {
        float4 a = fs[h * 32 + lane];
        float4 b = fd[h * 32 + lane];
        float4 w = at[h * 32 + lane];
        float v = lrelu(a.x + b.x) * w.x + lrelu(a.y + b.y) * w.y
                + lrelu(a.z + b.z) * w.z + lrelu(a.w + b.w) * w.w;
        #pragma unroll
        for (int o = 16; o; o >>= 1) v += __shfl_xor_sync(0xffffffffu, v, o);
        if (lane == 0) g_sc1[(size_t)gw * HH + h] = v;
    }
}

// ---------------- layer-1 softmax + aggregation + ELU: block(128) per node ----
__global__ void agg1(const int* __restrict__ src)
{
    int n    = blockIdx.x;
    int tid  = threadIdx.x;
    int lane = tid & 31;
    int w    = tid >> 5;         // head id
    __shared__ float sm[HH], sinv[HH];
    int rs  = g_rs[n];
    int deg = g_rs[n + 1] - rs;

    float mx = -1e30f;
    for (int i = lane; i < deg; i += 32)
        mx = fmaxf(mx, g_sc1[(size_t)g_eid[rs + i] * HH + w]);
    #pragma unroll
    for (int o = 16; o; o >>= 1) mx = fmaxf(mx, __shfl_xor_sync(0xffffffffu, mx, o));
    float sum = 0.f;
    for (int i = lane; i < deg; i += 32)
        sum += __expf(g_sc1[(size_t)g_eid[rs + i] * HH + w] - mx);
    #pragma unroll
    for (int o = 16; o; o >>= 1) sum += __shfl_xor_sync(0xffffffffu, sum, o);
    if (lane == 0) { sm[w] = mx; sinv[w] = sum > 0.f ? 1.f / sum : 0.f; }
    __syncthreads();
    float m = sm[w], inv = sinv[w];

    float4 acc = make_float4(0.f, 0.f, 0.f, 0.f);
    for (int i = 0; i < deg; i++) {
        int e = g_eid[rs + i];
        float a = __expf(g_sc1[(size_t)e * HH + w] - m) * inv;
        float4 f = *(const float4*)(g_fs1 + (size_t)src[e] * D1 + tid * 4);
        acc.x = fmaf(a, f.x, acc.x);
        acc.y = fmaf(a, f.y, acc.y);
        acc.z = fmaf(a, f.z, acc.z);
        acc.w = fmaf(a, f.w, acc.w);
    }
    float4 o = make_float4(elu_f(acc.x), elu_f(acc.y), elu_f(acc.z), elu_f(acc.w));
    *(float4*)(g_h1 + (size_t)n * D1 + tid * 4) = o;
}

// ---------------- layer-2 edge scores: warp per edge ----------------
__global__ void score2(const int* __restrict__ src, const int* __restrict__ dst,
                       const float* __restrict__ attn)
{
    int gw   = (blockIdx.x * blockDim.x + threadIdx.x) >> 5;
    int lane = threadIdx.x & 31;
    if (gw >= NE) return;
    int s = src[gw], d = dst[gw];
    float4 a = *(const float4*)(g_fs2 + (size_t)s * FF + lane * 4);
    float4 b = *(const float4*)(g_fd2 + (size_t)d * FF + lane * 4);
    float4 w = *(const float4*)(attn + lane * 4);
    float v = lrelu(a.x + b.x) * w.x + lrelu(a.y + b.y) * w.y
            + lrelu(a.z + b.z) * w.z + lrelu(a.w + b.w) * w.w;
    #pragma unroll
    for (int o = 16; o; o >>= 1) v += __shfl_xor_sync(0xffffffffu, v, o);
    if (lane == 0) g_sc2[gw] = v;
}

// ---------------- layer-2 softmax + aggregation + ELU: warp per node ----------
__global__ void agg2(const int* __restrict__ src)
{
    int n    = blockIdx.x * 8 + (threadIdx.x >> 5);
    int lane = threadIdx.x & 31;
    int rs   = g_rs[n];
    int deg  = g_rs[n + 1] - rs;

    float mx = -1e30f;
    for (int i = lane; i < deg; i += 32)
        mx = fmaxf(mx, g_sc2[g_eid[rs + i]]);
    #pragma unroll
    for (int o = 16; o; o >>= 1) mx = fmaxf(mx, __shfl_xor_sync(0xffffffffu, mx, o));
    float sum = 0.f;
    for (int i = lane; i < deg; i += 32)
        sum += __expf(g_sc2[g_eid[rs + i]] - mx);
    #pragma unroll
    for (int o = 16; o; o >>= 1) sum += __shfl_xor_sync(0xffffffffu, sum, o);
    float inv = sum > 0.f ? 1.f / sum : 0.f;

    float4 acc = make_float4(0.f, 0.f, 0.f, 0.f);
    for (int i = 0; i < deg; i++) {
        int e = g_eid[rs + i];
        float a = __expf(g_sc2[e] - mx) * inv;
        float4 f = *(const float4*)(g_fs2 + (size_t)src[e] * FF + lane * 4);
        acc.x = fmaf(a, f.x, acc.x);
        acc.y = fmaf(a, f.y, acc.y);
        acc.z = fmaf(a, f.z, acc.z);
        acc.w = fmaf(a, f.w, acc.w);
    }
    float4 o = make_float4(elu_f(acc.x), elu_f(acc.y), elu_f(acc.z), elu_f(acc.w));
    *(float4*)(g_h2 + (size_t)n * FF + lane * 4) = o;
}

// ---------------- launch ----------------
extern "C" void kernel_launch(void* const* d_in, const int* in_sizes, int n_in,
                              void* d_out, int out_size)
{
    const float* feat  = (const float*)d_in[0];
    const int*   src   = (const int*)  d_in[1];
    const int*   dst   = (const int*)  d_in[2];
    const float* W1s   = (const float*)d_in[3];
    const float* b1s   = (const float*)d_in[4];
    const float* W1d   = (const float*)d_in[5];
    const float* b1d   = (const float*)d_in[6];
    const float* attn1 = (const float*)d_in[7];
    const float* W2s   = (const float*)d_in[8];
    const float* b2s   = (const float*)d_in[9];
    const float* W2d   = (const float*)d_in[10];
    const float* b2d   = (const float*)d_in[11];
    const float* attn2 = (const float*)d_in[12];
    const float* Wn    = (const float*)d_in[13];
    const float* bn    = (const float*)d_in[14];
    float* out = (float*)d_out;

    float *fs1, *fd1, *h1, *fs2, *fd2, *h2, *part;
    cudaGetSymbolAddress((void**)&fs1,  g_fs1);
    cudaGetSymbolAddress((void**)&fd1,  g_fd1);
    cudaGetSymbolAddress((void**)&h1,   g_h1);
    cudaGetSymbolAddress((void**)&fs2,  g_fs2);
    cudaGetSymbolAddress((void**)&fd2,  g_fd2);
    cudaGetSymbolAddress((void**)&h2,   g_h2);
    cudaGetSymbolAddress((void**)&part, g_part);

    // layer-1 projections: [16384,128] @ [128,512]  (mma.sync bf16 3-term)
    gemm_mma<<<dim3(D1 / 128, NN / 128), 256>>>(feat, W1s, b1s, fs1, NN, D1, FF);
    gemm_mma<<<dim3(D1 / 128, NN / 128), 256>>>(feat, W1d, b1d, fd1, NN, D1, FF);

    // CSR by dst
    csr_zero   <<<NN / 256, 256>>>();
    csr_hist   <<<NE / 256, 256>>>(dst);
    csr_scan   <<<1, 1024>>>();
    csr_scatter<<<NE / 256, 256>>>(dst);

    // layer-1 edge softmax + aggregation (+ ELU)
    score1<<<NE / 8, 256>>>(src, dst, attn1);
    agg1  <<<NN, 128>>>(src);

    // layer-2 projections: [16384,512] @ [512,128]  (mma.sync bf16 3-term)
    gemm_mma<<<dim3(FF / 128, NN / 128), 256>>>(h1, W2s, b2s, fs2, NN, FF, D1);
    gemm_mma<<<dim3(FF / 128, NN / 128), 256>>>(h1, W2d, b2d, fd2, NN, FF, D1);

    // layer-2 edge softmax + aggregation (+ ELU)
    score2<<<NE / 8, 256>>>(src, dst, attn2);
    agg2  <<<NN / 8, 256>>>(src);

    // head: [256, 8192] @ [8192, 128] + bn — 32-way split-K then reduce
    gemm_sk<<<dim3(1, 2, SK), 256>>>(h2, Wn, part, 256, FF, 64 * FF, (64 * FF) / SK);
    sk_reduce<<<(256 * FF) / 256, 256>>>(part, bn, out, 256 * FF, FF, SK);
}